// round 14
// baseline (speedup 1.0000x reference)
#include <cuda_runtime.h>
#include <cuda_bf16.h>

// EmbLoss: B=16, H=W=640, C=4, 8 labels. Output: 1 float scalar.
// Inputs: emb f32 [B,H,W,4], instance i32, kernel f32, training_mask f32.

#define BB   16
#define HW_  (640*640)
#define HW4_ (HW_/4)
#define GX1  55     // pass1 blocks per b -> 880 total ~ 6/SM (reg-limit fit)
#define GXP2 32     // pass2 blocks per b (proven at LTS floor)
#define NT   256

// Scratch (__device__ globals; zero at load, re-zeroed at end of k_final).
__device__ float g_sum[BB][8][5];   // [l][0..3]=kernel-region emb sums, [4]=count
__device__ float g_cnti[BB][8];     // per-label pixel counts (tm-masked instance)
__device__ float g_agg[BB];         // pre-weighted aggregation sums (= l_agg)

// packed float2 add (Blackwell f32x2 pipe)
#define PADD2(a, b) asm volatile("add.rn.f32x2 %0, %0, %1;" : "+l"(a) : "l"(b))

// ---------------------------------------------------------------------------
// Pass 1: coalesced loads + per-thread SMEM label slots (labels 1..7 only;
// key==0 predicated off — label 0 sums are never read).
__global__ __launch_bounds__(NT, 6) void k_pass1(
    const ulonglong2* __restrict__ emb, const int* __restrict__ inst,
    const float* __restrict__ ker, const float* __restrict__ tmk)
{
    __shared__ ulonglong2 slots[7][NT];       // 28 KB: slots[label-1][tid]
    const int tid = threadIdx.x;
#pragma unroll
    for (int l = 0; l < 7; l++) slots[l][tid] = make_ulonglong2(0ull, 0ull);
    __syncthreads();

    const int b = blockIdx.y;
    const int base = b * HW_;
    const int STR = GX1 * NT;                 // 14080
    unsigned ck0 = 0, ck1 = 0, cl0 = 0, cl1 = 0;   // byte-packed counters
    // pixels/thread <= 32 -> byte counters never overflow

    for (int p0 = blockIdx.x * NT + tid; p0 < HW_; p0 += 4 * STR) {
        ulonglong2 ev[4];
        int        li[4];
        float      kf[4], tf[4];
        bool       ok[4];
#pragma unroll
        for (int j = 0; j < 4; j++) {
            int p = p0 + j * STR;
            ok[j] = (p < HW_);
            int q = ok[j] ? (base + p) : base;
            ev[j] = emb[q];              // coalesced LDG.128
            li[j] = inst[q];             // coalesced LDG.32
            kf[j] = ker[q];
            tf[j] = tmk[q];
        }
#pragma unroll
        for (int j = 0; j < 4; j++) {
            if (!ok[j]) continue;
            int lab = (tf[j] > 0.5f) ? (li[j] & 7) : 0;
            int key = (kf[j] > 0.5f) ? lab : 0;
            if (key != 0) {                   // short arm -> predicated
                ulonglong2 s = slots[key - 1][tid];   // LDS.128
                PADD2(s.x, ev[j].x);
                PADD2(s.y, ev[j].y);
                slots[key - 1][tid] = s;              // STS.128
            }
            unsigned incK = 1u << ((key & 3) << 3);
            if (key < 4) ck0 += incK; else ck1 += incK;
            unsigned incL = 1u << ((lab & 3) << 3);
            if (lab < 4) cl0 += incL; else cl1 += incL;
        }
    }
    __syncthreads();

    // Reduce emb slots: warp w owns label w+1 (warp 7 idle here).
    const int w = tid >> 5, lane = tid & 31;
    if (w < 7) {
        ulonglong2 acc = slots[w][lane];
#pragma unroll
        for (int j = 1; j < NT / 32; j++) {
            ulonglong2 t = slots[w][lane + j * 32];
            PADD2(acc.x, t.x);
            PADD2(acc.y, t.y);
        }
#pragma unroll
        for (int o = 16; o; o >>= 1) {
            unsigned long long t = __shfl_xor_sync(0xffffffffu, acc.x, o);
            PADD2(acc.x, t);
            unsigned long long u = __shfl_xor_sync(0xffffffffu, acc.y, o);
            PADD2(acc.y, u);
        }
        if (lane == 0) {
            atomicAdd(&g_sum[b][w+1][0], __uint_as_float((unsigned)(acc.x & 0xffffffffu)));
            atomicAdd(&g_sum[b][w+1][1], __uint_as_float((unsigned)(acc.x >> 32)));
            atomicAdd(&g_sum[b][w+1][2], __uint_as_float((unsigned)(acc.y & 0xffffffffu)));
            atomicAdd(&g_sum[b][w+1][3], __uint_as_float((unsigned)(acc.y >> 32)));
        }
    }

    // Counts: per-warp butterflies; EVERY warp's lane 0 contributes.
    float ckf[7], clf[6];
#pragma unroll
    for (int l = 1; l < 8; l++)
        ckf[l-1] = (float)((l < 4 ? (ck0 >> (l*8)) : (ck1 >> ((l-4)*8))) & 255u);
#pragma unroll
    for (int l = 2; l < 8; l++)
        clf[l-2] = (float)((l < 4 ? (cl0 >> (l*8)) : (cl1 >> ((l-4)*8))) & 255u);
#pragma unroll
    for (int j = 0; j < 7; j++) {
#pragma unroll
        for (int o = 16; o; o >>= 1) ckf[j] += __shfl_xor_sync(0xffffffffu, ckf[j], o);
    }
#pragma unroll
    for (int j = 0; j < 6; j++) {
#pragma unroll
        for (int o = 16; o; o >>= 1) clf[j] += __shfl_xor_sync(0xffffffffu, clf[j], o);
    }
    if (lane == 0) {
#pragma unroll
        for (int l = 0; l < 7; l++) atomicAdd(&g_sum[b][l+1][4], ckf[l]);
#pragma unroll
        for (int l = 0; l < 6; l++) atomicAdd(&g_cnti[b][l+2], clf[l]);
    }
}

// ---------------------------------------------------------------------------
// Pass 2 (proven form): int4/float4 wide loads, 4 contiguous px/thread-iter.
__global__ __launch_bounds__(NT) void k_pass2(
    const float4* __restrict__ emb, const int4* __restrict__ inst,
    const float4* __restrict__ tmk)
{
    __shared__ float4 s_nmu[8];   // NEGATED means
    __shared__ float  s_w[8];
    const int b = blockIdx.y;
    if (threadIdx.x < 8) {
        int l = threadIdx.x;
        float4 m = make_float4(0.f, 0.f, 0.f, 0.f);
        if (l > 0) {
            float r = -1.0f / fmaxf(g_sum[b][l][4], 1.0f);
            m.x = g_sum[b][l][0] * r; m.y = g_sum[b][l][1] * r;
            m.z = g_sum[b][l][2] * r; m.w = g_sum[b][l][3] * r;
        }
        s_nmu[l] = m;
        s_w[l] = (l >= 2) ? 1.0f / (6.0f * fmaxf(g_cnti[b][l], 1.0f)) : 0.0f;
    }
    __syncthreads();

    float acc = 0.0f;
    const int base = b * HW4_;
    for (int i = blockIdx.x * NT + threadIdx.x; i < HW4_; i += GXP2 * NT) {
        int4   iv = inst[base + i];
        float4 tv = tmk[base + i];
#pragma unroll
        for (int k = 0; k < 4; k++) {
            int   li = (k==0) ? iv.x : (k==1) ? iv.y : (k==2) ? iv.z : iv.w;
            float tf = (k==0) ? tv.x : (k==1) ? tv.y : (k==2) ? tv.z : tv.w;
            float4 e = emb[(base + i) * 4 + k];
            int lab = (tf > 0.5f) ? (li & 7) : 0;
            float4 m = s_nmu[lab];
            float  w = s_w[lab];
            float dx = e.x + m.x, dy = e.y + m.y, dz = e.z + m.z, dw = e.w + m.w;
            float sq = dx*dx;
            sq = fmaf(dy, dy, sq); sq = fmaf(dz, dz, sq); sq = fmaf(dw, dw, sq);
            float d;
            asm("sqrt.approx.f32 %0, %1;" : "=f"(d) : "f"(sq));
            float t = fmaxf(d - 0.5f, 0.0f);              // DELTA_V
            float term = __logf(fmaf(t, t, 1.0f));
            acc = fmaf(term, w, acc);
        }
    }
#pragma unroll
    for (int o = 16; o; o >>= 1) acc += __shfl_xor_sync(0xffffffffu, acc, o);
    if ((threadIdx.x & 31u) == 0) atomicAdd(&g_agg[b], acc);
}

// Finalize + re-zero scratch for the next call (state invariant per launch).
__global__ void k_final(float* __restrict__ out) {
    __shared__ float sl[BB];
    int t = threadIdx.x;
    if (t < BB) {
        int b = t;
        float mu[8][4];
#pragma unroll
        for (int c = 0; c < 4; c++) mu[0][c] = 0.f;
#pragma unroll
        for (int l = 1; l < 8; l++) {
            float r = 1.0f / fmaxf(g_sum[b][l][4], 1.0f);
#pragma unroll
            for (int c = 0; c < 4; c++) mu[l][c] = g_sum[b][l][c] * r;
        }
        float la = g_agg[b];
        float ld = 0.f;
#pragma unroll
        for (int i2 = 1; i2 < 8; i2++)
#pragma unroll
            for (int j2 = 1; j2 < 8; j2++)
                if (i2 != j2) {
                    float sq = 0.f;
#pragma unroll
                    for (int c = 0; c < 4; c++) {
                        float d = mu[i2][c] - mu[j2][c];
                        sq = fmaf(d, d, sq);
                    }
                    float dd = (sq > 0.f) ? sqrtf(sq) : 0.f;
                    float tt = fmaxf(3.0f - dd, 0.0f);    // 2*DELTA_D
                    ld += __logf(fmaf(tt, tt, 1.0f));
                }
        ld *= (1.0f / 42.0f);
        float lr = 0.f;
#pragma unroll
        for (int l = 0; l < 8; l++) {
            float sq = 0.f;
#pragma unroll
            for (int c = 0; c < 4; c++) sq = fmaf(mu[l][c], mu[l][c], sq);
            float n = (sq > 0.f) ? sqrtf(sq) : 0.f;
            lr += __logf(n + 1.0f);
        }
        lr *= (0.001f / 8.0f);
        sl[b] = la + ld + lr;
    }
    __syncthreads();
    if (t == 0) {
        float s = 0.f;
#pragma unroll
        for (int i = 0; i < BB; i++) s += sl[i];
        out[0] = s * (1.0f / BB);            // LOSS_WEIGHT = 1
    }
    // re-zero scratch (reads above ordered by __syncthreads)
    {
        float* p = &g_sum[0][0][0];
        for (int j = t; j < BB*8*5; j += blockDim.x) p[j] = 0.f;
        float* q = &g_cnti[0][0];
        for (int j = t; j < BB*8; j += blockDim.x) q[j] = 0.f;
        if (t < BB) g_agg[t] = 0.f;
    }
}

extern "C" void kernel_launch(void* const* d_in, const int* in_sizes, int n_in,
                              void* d_out, int out_size) {
    (void)in_sizes; (void)n_in; (void)out_size;
    // Prefer max shared-memory carveout so 6 blocks/SM of k_pass1 fit.
    // (Attribute set is a non-stream API: capture-legal, idempotent,
    //  deterministic; error intentionally ignored.)
    cudaFuncSetAttribute((const void*)k_pass1,
                         cudaFuncAttributePreferredSharedMemoryCarveout, 100);
    k_pass1<<<dim3(GX1, BB), NT>>>((const ulonglong2*)d_in[0], (const int*)d_in[1],
                                   (const float*)d_in[2],      (const float*)d_in[3]);
    k_pass2<<<dim3(GXP2, BB), NT>>>((const float4*)d_in[0], (const int4*)d_in[1],
                                    (const float4*)d_in[3]);
    k_final<<<1, 128>>>((float*)d_out);
}

// round 16
// speedup vs baseline: 1.2340x; 1.2340x over previous
#include <cuda_runtime.h>
#include <cuda_bf16.h>

// EmbLoss: B=16, H=W=640, C=4, 8 labels. Output: 1 float scalar.
// Inputs: emb f32 [B,H,W,4], instance i32, kernel f32, training_mask f32.

#define BB   16
#define HW_  (640*640)
#define HW4_ (HW_/4)
#define GX1  27     // pass1 blocks per b -> 432 total ~ 3/SM (reg-heavy pipeline)
#define GXP2 32     // pass2 blocks per b (proven at LTS floor)
#define NT   256
#define STR1 (GX1 * NT)                 // 6912
#define ITER1 ((HW_ + 4*STR1 - 1) / (4*STR1))   // 15 uniform iterations

// Scratch (__device__ globals; zero at load, re-zeroed at end of k_final).
__device__ float g_sum[BB][8][5];   // [l][0..3]=kernel-region emb sums, [4]=count
__device__ float g_cnti[BB][8];     // per-label pixel counts (tm-masked instance)
__device__ float g_agg[BB];         // pre-weighted aggregation sums (= l_agg)

// packed float2 add (Blackwell f32x2 pipe)
#define PADD2(a, b) asm volatile("add.rn.f32x2 %0, %0, %1;" : "+l"(a) : "l"(b))

struct Grp {                       // one iteration's 4 pixels (28 regs)
    ulonglong2 ev[4];
    int        li[4];
    float      kf[4], tf[4];
};

// ---------------------------------------------------------------------------
// Pass 1: coalesced loads, explicit 2-deep pipeline (MLP=16), per-thread SMEM
// label slots (8 labels, unconditional RMW — no divergent branch).
__global__ __launch_bounds__(NT, 3) void k_pass1(
    const ulonglong2* __restrict__ emb, const int* __restrict__ inst,
    const float* __restrict__ ker, const float* __restrict__ tmk)
{
    __shared__ ulonglong2 slots[8][NT];       // 32 KB: slots[label][tid]
    const int tid = threadIdx.x;
#pragma unroll
    for (int l = 0; l < 8; l++) slots[l][tid] = make_ulonglong2(0ull, 0ull);
    __syncthreads();

    const int b = blockIdx.y;
    const int base = b * HW_;
    unsigned ck0 = 0, ck1 = 0, cl0 = 0, cl1 = 0;   // byte-packed counters
    // pixels/thread <= 60 -> byte counters never overflow

    const int p_start = blockIdx.x * NT + tid;

    // load one 4-pixel group (16 independent loads, OOB clamped to base)
    auto load_grp = [&](Grp& g, int p0) {
#pragma unroll
        for (int j = 0; j < 4; j++) {
            int p = p0 + j * STR1;
            int q = (p < HW_) ? (base + p) : base;
            g.ev[j] = emb[q];            // coalesced LDG.128
            g.li[j] = inst[q];           // coalesced LDG.32
            g.kf[j] = ker[q];
            g.tf[j] = tmk[q];
        }
    };
    // process one group (recompute OOB mask from p0)
    auto proc_grp = [&](const Grp& g, int p0) {
#pragma unroll
        for (int j = 0; j < 4; j++) {
            if (p0 + j * STR1 >= HW_) continue;
            int lab = (g.tf[j] > 0.5f) ? (g.li[j] & 7) : 0;
            int key = (g.kf[j] > 0.5f) ? lab : 0;
            ulonglong2 s = slots[key][tid];   // LDS.128 (banks = f(tid) only)
            PADD2(s.x, g.ev[j].x);
            PADD2(s.y, g.ev[j].y);
            slots[key][tid] = s;              // STS.128
            unsigned incK = 1u << ((key & 3) << 3);
            if (key < 4) ck0 += incK; else ck1 += incK;
            unsigned incL = 1u << ((lab & 3) << 3);
            if (lab < 4) cl0 += incL; else cl1 += incL;
        }
    };

    Grp cur, nxt;
    int p0 = p_start;
    load_grp(cur, p0);
    for (int it = 0; it < ITER1 - 1; ++it) {
        load_grp(nxt, p0 + 4 * STR1);    // prefetch next group (MLP=16)
        proc_grp(cur, p0);
        cur = nxt;
        p0 += 4 * STR1;
    }
    proc_grp(cur, p0);
    __syncthreads();

    // Reduce emb slots: warp w owns label w.
    const int w = tid >> 5, lane = tid & 31;
    ulonglong2 acc = slots[w][lane];
#pragma unroll
    for (int j = 1; j < NT / 32; j++) {
        ulonglong2 t = slots[w][lane + j * 32];
        PADD2(acc.x, t.x);
        PADD2(acc.y, t.y);
    }
#pragma unroll
    for (int o = 16; o; o >>= 1) {
        unsigned long long t = __shfl_xor_sync(0xffffffffu, acc.x, o);
        PADD2(acc.x, t);
        unsigned long long u = __shfl_xor_sync(0xffffffffu, acc.y, o);
        PADD2(acc.y, u);
    }
    if (lane == 0 && w > 0) {
        atomicAdd(&g_sum[b][w][0], __uint_as_float((unsigned)(acc.x & 0xffffffffu)));
        atomicAdd(&g_sum[b][w][1], __uint_as_float((unsigned)(acc.x >> 32)));
        atomicAdd(&g_sum[b][w][2], __uint_as_float((unsigned)(acc.y & 0xffffffffu)));
        atomicAdd(&g_sum[b][w][3], __uint_as_float((unsigned)(acc.y >> 32)));
    }

    // Counts: per-warp butterflies; EVERY warp's lane 0 contributes.
    float ckf[7], clf[6];
#pragma unroll
    for (int l = 1; l < 8; l++)
        ckf[l-1] = (float)((l < 4 ? (ck0 >> (l*8)) : (ck1 >> ((l-4)*8))) & 255u);
#pragma unroll
    for (int l = 2; l < 8; l++)
        clf[l-2] = (float)((l < 4 ? (cl0 >> (l*8)) : (cl1 >> ((l-4)*8))) & 255u);
#pragma unroll
    for (int j = 0; j < 7; j++) {
#pragma unroll
        for (int o = 16; o; o >>= 1) ckf[j] += __shfl_xor_sync(0xffffffffu, ckf[j], o);
    }
#pragma unroll
    for (int j = 0; j < 6; j++) {
#pragma unroll
        for (int o = 16; o; o >>= 1) clf[j] += __shfl_xor_sync(0xffffffffu, clf[j], o);
    }
    if (lane == 0) {
#pragma unroll
        for (int l = 0; l < 7; l++) atomicAdd(&g_sum[b][l+1][4], ckf[l]);
#pragma unroll
        for (int l = 0; l < 6; l++) atomicAdd(&g_cnti[b][l+2], clf[l]);
    }
}

// ---------------------------------------------------------------------------
// Pass 2 (proven form): int4/float4 wide loads, 4 contiguous px/thread-iter.
__global__ __launch_bounds__(NT) void k_pass2(
    const float4* __restrict__ emb, const int4* __restrict__ inst,
    const float4* __restrict__ tmk)
{
    __shared__ float4 s_nmu[8];   // NEGATED means
    __shared__ float  s_w[8];
    const int b = blockIdx.y;
    if (threadIdx.x < 8) {
        int l = threadIdx.x;
        float4 m = make_float4(0.f, 0.f, 0.f, 0.f);
        if (l > 0) {
            float r = -1.0f / fmaxf(g_sum[b][l][4], 1.0f);
            m.x = g_sum[b][l][0] * r; m.y = g_sum[b][l][1] * r;
            m.z = g_sum[b][l][2] * r; m.w = g_sum[b][l][3] * r;
        }
        s_nmu[l] = m;
        s_w[l] = (l >= 2) ? 1.0f / (6.0f * fmaxf(g_cnti[b][l], 1.0f)) : 0.0f;
    }
    __syncthreads();

    float acc = 0.0f;
    const int base = b * HW4_;
    for (int i = blockIdx.x * NT + threadIdx.x; i < HW4_; i += GXP2 * NT) {
        int4   iv = inst[base + i];
        float4 tv = tmk[base + i];
#pragma unroll
        for (int k = 0; k < 4; k++) {
            int   li = (k==0) ? iv.x : (k==1) ? iv.y : (k==2) ? iv.z : iv.w;
            float tf = (k==0) ? tv.x : (k==1) ? tv.y : (k==2) ? tv.z : tv.w;
            float4 e = emb[(base + i) * 4 + k];
            int lab = (tf > 0.5f) ? (li & 7) : 0;
            float4 m = s_nmu[lab];
            float  w = s_w[lab];
            float dx = e.x + m.x, dy = e.y + m.y, dz = e.z + m.z, dw = e.w + m.w;
            float sq = dx*dx;
            sq = fmaf(dy, dy, sq); sq = fmaf(dz, dz, sq); sq = fmaf(dw, dw, sq);
            float d;
            asm("sqrt.approx.f32 %0, %1;" : "=f"(d) : "f"(sq));
            float t = fmaxf(d - 0.5f, 0.0f);              // DELTA_V
            float term = __logf(fmaf(t, t, 1.0f));
            acc = fmaf(term, w, acc);
        }
    }
#pragma unroll
    for (int o = 16; o; o >>= 1) acc += __shfl_xor_sync(0xffffffffu, acc, o);
    if ((threadIdx.x & 31u) == 0) atomicAdd(&g_agg[b], acc);
}

// Finalize + re-zero scratch for the next call (state invariant per launch).
__global__ void k_final(float* __restrict__ out) {
    __shared__ float sl[BB];
    int t = threadIdx.x;
    if (t < BB) {
        int b = t;
        float mu[8][4];
#pragma unroll
        for (int c = 0; c < 4; c++) mu[0][c] = 0.f;
#pragma unroll
        for (int l = 1; l < 8; l++) {
            float r = 1.0f / fmaxf(g_sum[b][l][4], 1.0f);
#pragma unroll
            for (int c = 0; c < 4; c++) mu[l][c] = g_sum[b][l][c] * r;
        }
        float la = g_agg[b];
        float ld = 0.f;
#pragma unroll
        for (int i2 = 1; i2 < 8; i2++)
#pragma unroll
            for (int j2 = 1; j2 < 8; j2++)
                if (i2 != j2) {
                    float sq = 0.f;
#pragma unroll
                    for (int c = 0; c < 4; c++) {
                        float d = mu[i2][c] - mu[j2][c];
                        sq = fmaf(d, d, sq);
                    }
                    float dd = (sq > 0.f) ? sqrtf(sq) : 0.f;
                    float tt = fmaxf(3.0f - dd, 0.0f);    // 2*DELTA_D
                    ld += __logf(fmaf(tt, tt, 1.0f));
                }
        ld *= (1.0f / 42.0f);
        float lr = 0.f;
#pragma unroll
        for (int l = 0; l < 8; l++) {
            float sq = 0.f;
#pragma unroll
            for (int c = 0; c < 4; c++) sq = fmaf(mu[l][c], mu[l][c], sq);
            float n = (sq > 0.f) ? sqrtf(sq) : 0.f;
            lr += __logf(n + 1.0f);
        }
        lr *= (0.001f / 8.0f);
        sl[b] = la + ld + lr;
    }
    __syncthreads();
    if (t == 0) {
        float s = 0.f;
#pragma unroll
        for (int i = 0; i < BB; i++) s += sl[i];
        out[0] = s * (1.0f / BB);            // LOSS_WEIGHT = 1
    }
    // re-zero scratch (reads above ordered by __syncthreads)
    {
        float* p = &g_sum[0][0][0];
        for (int j = t; j < BB*8*5; j += blockDim.x) p[j] = 0.f;
        float* q = &g_cnti[0][0];
        for (int j = t; j < BB*8; j += blockDim.x) q[j] = 0.f;
        if (t < BB) g_agg[t] = 0.f;
    }
}

extern "C" void kernel_launch(void* const* d_in, const int* in_sizes, int n_in,
                              void* d_out, int out_size) {
    (void)in_sizes; (void)n_in; (void)out_size;
    k_pass1<<<dim3(GX1, BB), NT>>>((const ulonglong2*)d_in[0], (const int*)d_in[1],
                                   (const float*)d_in[2],      (const float*)d_in[3]);
    k_pass2<<<dim3(GXP2, BB), NT>>>((const float4*)d_in[0], (const int4*)d_in[1],
                                    (const float4*)d_in[3]);
    k_final<<<1, 128>>>((float*)d_out);
}